// round 13
// baseline (speedup 1.0000x reference)
#include <cuda_runtime.h>
#include <cuda_fp16.h>
#include <math.h>
#include <stdint.h>

#define N_NODES 8192
#define N_BONDS 16384
#define EMBED 32
#define HIDDEN 256
#define DEPTH 10
#define NUM_GRAPHS 256

// ---------------- static device scratch ----------------
// A image: 4-bit {0,1}, fragment-ordered for mma.m16n8k16.f16.
// Block (mb 0..511, kc 0..63) = 1024B: [lane 32][kt 8][4B word].
//   word(kt) byte i: lo-nib = v(r, kk[i]), hi-nib = v(r+8, kk[i])
//   r = lane>>2, k0 = kc*128 + kt*16 + (lane&3)*2, kk = {k0, k0+1, k0+8, k0+9}.
__device__ __align__(16) uint8_t g_A4[(size_t)512 * 64 * 1024];  // 32MB
__device__ __align__(16) __half g_hq[(size_t)N_NODES * EMBED];   // [j][e] fp16
__device__ __align__(16) float g_h[N_NODES * EMBED];
__device__ __align__(16) float g_neip[4][N_NODES * EMBED];       // [kq][node][e]
__device__ __align__(16) float g_Wc[DEPTH][96 * 64];             // composed, [gate][k=64]
__device__ float g_bc[DEPTH][96];                                // Wih@msg_b
__device__ float g_deg[N_NODES];
__device__ float g_pool_sum[NUM_GRAPHS * EMBED];
__device__ float g_pool_cnt[NUM_GRAPHS];

// ---------------- PTX helpers ----------------
__device__ __forceinline__ uint32_t smem_u32(const void* p) {
    uint32_t a;
    asm("{ .reg .u64 t; cvta.to.shared.u64 t, %1; cvt.u32.u64 %0, t; }" : "=r"(a) : "l"(p));
    return a;
}
__device__ __forceinline__ uint32_t prmt0(uint32_t a, uint32_t sel) {
    uint32_t d;
    asm("prmt.b32 %0, %1, 0, %2;" : "=r"(d) : "r"(a), "r"(sel));
    return d;
}
__device__ __forceinline__ void cp16(uint32_t dst, const void* src) {
    asm volatile("cp.async.cg.shared.global [%0], [%1], 16;" :: "r"(dst), "l"(src));
}
__device__ __forceinline__ void lds128(uint4& v, uint32_t addr) {
    asm volatile("ld.shared.v4.u32 {%0,%1,%2,%3}, [%4];"
                 : "=r"(v.x), "=r"(v.y), "=r"(v.z), "=r"(v.w) : "r"(addr));
}
__device__ __forceinline__ void ldm_x4_trans(uint32_t* r, uint32_t addr) {
    asm volatile("ldmatrix.sync.aligned.m8n8.x4.trans.shared.b16 {%0,%1,%2,%3}, [%4];"
                 : "=r"(r[0]), "=r"(r[1]), "=r"(r[2]), "=r"(r[3]) : "r"(addr));
}
__device__ __forceinline__ void mma_f16(float* c, uint32_t a0, uint32_t a1,
                                        uint32_t a2, uint32_t a3,
                                        uint32_t b0, uint32_t b1) {
    asm volatile(
        "mma.sync.aligned.m16n8k16.row.col.f32.f16.f16.f32 "
        "{%0,%1,%2,%3}, {%4,%5,%6,%7}, {%8,%9}, {%0,%1,%2,%3};"
        : "+f"(c[0]), "+f"(c[1]), "+f"(c[2]), "+f"(c[3])
        : "r"(a0), "r"(a1), "r"(a2), "r"(a3), "r"(b0), "r"(b1));
}

// ---------------- init ----------------
__global__ void k_init(const int* __restrict__ af, const int* __restrict__ bf,
                       const float* __restrict__ atab, const float* __restrict__ btab,
                       float* __restrict__ out) {
    int idx = blockIdx.x * 256 + threadIdx.x;
    if (idx < N_BONDS * EMBED)
        out[N_NODES * EMBED + idx] = btab[bf[idx >> 5] * EMBED + (idx & 31)];
    if (idx < N_NODES * EMBED) {
        float h = atab[af[idx >> 5] * EMBED + (idx & 31)];
        g_h[idx] = h;
        g_hq[idx] = __float2half_rn(h);
    }
    if (idx < N_NODES) g_deg[idx] = 0.f;
    if (idx < NUM_GRAPHS * EMBED) g_pool_sum[idx] = 0.f;
    if (idx < NUM_GRAPHS) g_pool_cnt[idx] = 0.f;
}

// ---------------- adjacency -> 4-bit fragment-ordered image + degree ----------------
__global__ void __launch_bounds__(256) k_convA(const int* __restrict__ adj) {
    int t = threadIdx.x, lane = t & 31, w = t >> 5;
    int mb = blockIdx.x;
    int kc = blockIdx.y * 8 + w;
    int r = lane >> 2, kq = (lane & 3) * 2;
    int row0 = mb * 16;
    uint8_t* dst = g_A4 + (((size_t)mb * 64 + kc) * 1024) + (size_t)lane * 32;
    int cnt0 = 0, cnt8 = 0;
    uint32_t wv[8];
#pragma unroll
    for (int kt = 0; kt < 8; kt++) {
        int k0 = kc * 128 + kt * 16 + kq;
        int2 p00 = *(const int2*)&adj[(size_t)(row0 + r) * N_NODES + k0];
        int2 p08 = *(const int2*)&adj[(size_t)(row0 + r) * N_NODES + k0 + 8];
        int2 p80 = *(const int2*)&adj[(size_t)(row0 + r + 8) * N_NODES + k0];
        int2 p88 = *(const int2*)&adj[(size_t)(row0 + r + 8) * N_NODES + k0 + 8];
        uint32_t b0 = (p00.x != 0), b1 = (p00.y != 0);
        uint32_t b2 = (p08.x != 0), b3 = (p08.y != 0);
        uint32_t c0 = (p80.x != 0), c1 = (p80.y != 0);
        uint32_t c2 = (p88.x != 0), c3 = (p88.y != 0);
        cnt0 += b0 + b1 + b2 + b3;
        cnt8 += c0 + c1 + c2 + c3;
        wv[kt] = b0 | (c0 << 4) | (b1 << 8) | (c1 << 12) |
                 (b2 << 16) | (c2 << 20) | (b3 << 24) | (c3 << 28);
    }
    *(uint4*)(dst) = make_uint4(wv[0], wv[1], wv[2], wv[3]);
    *(uint4*)(dst + 16) = make_uint4(wv[4], wv[5], wv[6], wv[7]);
    cnt0 += __shfl_down_sync(0xffffffffu, cnt0, 2, 4);
    cnt0 += __shfl_down_sync(0xffffffffu, cnt0, 1, 4);
    cnt8 += __shfl_down_sync(0xffffffffu, cnt8, 2, 4);
    cnt8 += __shfl_down_sync(0xffffffffu, cnt8, 1, 4);
    if ((lane & 3) == 0) {
        atomicAdd(&g_deg[row0 + r], (float)cnt0);
        atomicAdd(&g_deg[row0 + r + 8], (float)cnt8);
    }
}

// ---------------- compose W_c = Wih @ Wmsg ([gate][k] layout), b_c = Wih @ msg_b ----
__global__ void __launch_bounds__(256) k_compose(const float* __restrict__ msgW,
                                                 const float* __restrict__ msgb,
                                                 const float* __restrict__ Wih) {
    int d = blockIdx.x, q = blockIdx.y;
    int t = threadIdx.x;
    const float* Wd = msgW + (size_t)d * 256 * 64;
    const float* Wi = Wih + (size_t)d * 96 * 256;
    for (int idx = t; idx < 24 * 64; idx += 256) {
        int g = q * 24 + (idx >> 6), e = idx & 63;
        float acc = 0.f;
#pragma unroll 4
        for (int k = 0; k < 256; k++) acc = fmaf(Wi[g * 256 + k], Wd[k * 64 + e], acc);
        g_Wc[d][g * 64 + e] = acc;  // [gate][k]
    }
    if (q == 0 && t < 96) {
        float acc = 0.f;
        for (int k = 0; k < 256; k++) acc = fmaf(Wi[t * 256 + k], msgb[d * 256 + k], acc);
        g_bc[d][t] = acc;
    }
}

// ---------------- nei partials = A @ h_fp16 via mma.sync f16 (R12 version) ----------
#define NEI_PITCH 80
#define NEI_STAGE 14336  // 4KB A + 10240B B (pitch 80), padded
#define NEI_SMEM (4 * NEI_STAGE)
#define NEI_CHUNKS 16
#define NIBM 0x0F0F0F0Fu
__global__ void __launch_bounds__(128, 4) k_neimma() {
    extern __shared__ uint8_t smem[];
    uint32_t sb = smem_u32(smem);
    int t = threadIdx.x, lane = t & 31, w = t >> 5;
    int mtile = blockIdx.x, kq = blockIdx.y;

    const uint8_t* Bbase = (const uint8_t*)g_hq + (size_t)kq * 2048 * 64;
    int apiece = t >> 5, aoff = (t & 31) * 32;
    const uint8_t* Asrc = g_A4 +
        ((size_t)((mtile * 4 + apiece) * 64 + kq * 16)) * 1024 + aoff;

#define LOADAB(c, s)                                                            \
    {                                                                           \
        uint32_t dst = sb + (s) * NEI_STAGE;                                    \
        cp16(dst + apiece * 1024 + aoff, Asrc + (size_t)(c) * 1024);            \
        cp16(dst + apiece * 1024 + aoff + 16, Asrc + (size_t)(c) * 1024 + 16);  \
        uint32_t dstb = dst + 4096;                                             \
        const uint8_t* srcb = Bbase + (size_t)(c) * 128 * 64;                   \
        _Pragma("unroll")                                                       \
        for (int i = 0; i < 4; i++) {                                           \
            int idx = t + i * 128;                                              \
            int row = idx >> 2, cg = idx & 3;                                   \
            cp16(dstb + row * NEI_PITCH + cg * 16, srcb + row * 64 + cg * 16);  \
        }                                                                       \
        asm volatile("cp.async.commit_group;");                                 \
    }

    LOADAB(0, 0);
    LOADAB(1, 1);
    LOADAB(2, 2);

    float acc[4][4];
#pragma unroll
    for (int p = 0; p < 4; p++)
#pragma unroll
        for (int i = 0; i < 4; i++) acc[p][i] = 0.f;

    int krb = lane & 15;
    int chi = lane >> 4;
    uint32_t aaddr_base = (uint32_t)(w * 1024 + lane * 32);
    uint32_t boff0 = (uint32_t)chi * 16;
    uint32_t boff1 = 32 + (uint32_t)chi * 16;

    for (int c = 0; c < NEI_CHUNKS; c++) {
        asm volatile("cp.async.wait_group 2;");
        __syncthreads();
        if (c + 3 < NEI_CHUNKS) LOADAB(c + 3, (c + 3) & 3);
        uint32_t sbase = sb + (c & 3) * NEI_STAGE;
        uint4 aw0, aw1;
        lds128(aw0, sbase + aaddr_base);
        lds128(aw1, sbase + aaddr_base + 16);
        uint32_t bb = sbase + 4096;

        uint32_t bf_cur[2][4], bf_nxt[2][4];
        {
            uint32_t rowaddr = bb + (uint32_t)krb * NEI_PITCH;
            ldm_x4_trans(bf_cur[0], rowaddr + boff0);
            ldm_x4_trans(bf_cur[1], rowaddr + boff1);
        }
#pragma unroll
        for (int kt = 0; kt < 8; kt++) {
            if (kt < 7) {
                uint32_t rowaddr = bb + (uint32_t)((kt + 1) * 16 + krb) * NEI_PITCH;
                ldm_x4_trans(bf_nxt[0], rowaddr + boff0);
                ldm_x4_trans(bf_nxt[1], rowaddr + boff1);
            }
            uint4 q = (kt & 4) ? aw1 : aw0;
            uint32_t wv = (kt & 2) ? ((kt & 1) ? q.w : q.z) : ((kt & 1) ? q.y : q.x);
            uint32_t lo = wv & NIBM;
            uint32_t hi = (wv >> 4) & NIBM;
            uint32_t a0 = prmt0(lo, 0x4140) * 0x3C00u;
            uint32_t a2 = prmt0(lo, 0x4342) * 0x3C00u;
            uint32_t a1 = prmt0(hi, 0x4140) * 0x3C00u;
            uint32_t a3 = prmt0(hi, 0x4342) * 0x3C00u;
            mma_f16(acc[0], a0, a1, a2, a3, bf_cur[0][0], bf_cur[0][1]);
            mma_f16(acc[1], a0, a1, a2, a3, bf_cur[0][2], bf_cur[0][3]);
            mma_f16(acc[2], a0, a1, a2, a3, bf_cur[1][0], bf_cur[1][1]);
            mma_f16(acc[3], a0, a1, a2, a3, bf_cur[1][2], bf_cur[1][3]);
            if (kt < 7) {
#pragma unroll
                for (int p = 0; p < 2; p++)
#pragma unroll
                    for (int i = 0; i < 4; i++) bf_cur[p][i] = bf_nxt[p][i];
            }
        }
    }

    float* base = g_neip[kq];
    int r = lane >> 2, c0 = (lane & 3) * 2;
    int node0 = mtile * 64 + w * 16 + r;
#pragma unroll
    for (int p = 0; p < 4; p++) {
        int col = p * 8 + c0;
        *(float2*)&base[(size_t)node0 * 32 + col] = make_float2(acc[p][0], acc[p][1]);
        *(float2*)&base[(size_t)(node0 + 8) * 32 + col] = make_float2(acc[p][2], acc[p][3]);
    }
#undef LOADAB
}

// ---------------- fused (composed msg+GRU), float4-vectorized gate GEMM ----------
// gi = bih + hasnei * (x @ W_c^T + b_c);  gh = h @ Whh^T + bhh
// 64 nodes/block, 128 blocks (single wave). Weights [gate][k], x loads broadcast.
#define WC_PITCH 68
#define WHH_PITCH 36
#define MSGRU_SMEM_FLOATS (64 * 68 + 96 * WC_PITCH + 96 * WHH_PITCH)
__global__ void __launch_bounds__(256) k_msgru(int d, int last,
                                               const float* __restrict__ Whh,
                                               const float* __restrict__ bih,
                                               const float* __restrict__ bhh,
                                               const int* __restrict__ bidx,
                                               float* __restrict__ out) {
    extern __shared__ float sm[];
    float* x_s = sm;                     // [64 nodes][68] : h(32) | nei_mean(32)
    float* wc_s = x_s + 64 * 68;         // [96 gates][WC_PITCH], k=0..63
    float* whh_s = wc_s + 96 * WC_PITCH; // [96 gates][WHH_PITCH], k=0..31
    int row0 = blockIdx.x * 64;
    int t = threadIdx.x;
    const float* Wc = g_Wc[d];
    const float* bc = g_bc[d];
    const float* bihd = bih + d * 96;
    const float* bhhd = bhh + d * 96;
    const float* Whhd = Whh + (size_t)d * 96 * 32;

    for (int idx = t; idx < 64 * EMBED; idx += 256) {
        int r = idx >> 5, e = idx & 31;
        int node = row0 + r;
        float invd = 1.0f / fmaxf(g_deg[node], 1.0f);
        int o = node * 32 + e;
        float s = g_neip[0][o] + g_neip[1][o] + g_neip[2][o] + g_neip[3][o];
        x_s[r * 68 + e] = g_h[o];
        x_s[r * 68 + 32 + e] = s * invd;
    }
    for (int idx = t; idx < 96 * 64; idx += 256) {
        int g = idx >> 6, k = idx & 63;
        wc_s[g * WC_PITCH + k] = Wc[idx];
    }
    for (int idx = t; idx < 96 * EMBED; idx += 256) {
        int g = idx >> 5, k = idx & 31;
        whh_s[g * WHH_PITCH + k] = Whhd[idx];
    }
    __syncthreads();

    int e = t & 31;
    int rb = (t >> 5) * 8;
    float gi[8][3], gh[8][3];
#pragma unroll
    for (int i = 0; i < 8; i++) {
        gi[i][0] = gi[i][1] = gi[i][2] = 0.f;
        gh[i][0] = gh[i][1] = gh[i][2] = 0.f;
    }
    // gi: k = 0..63 over x = [h|nei], weights [gate][k] -> float4 everywhere
    for (int k = 0; k < 64; k += 4) {
        float4 w0 = *(const float4*)&wc_s[e * WC_PITCH + k];
        float4 w1 = *(const float4*)&wc_s[(32 + e) * WC_PITCH + k];
        float4 w2 = *(const float4*)&wc_s[(64 + e) * WC_PITCH + k];
#pragma unroll
        for (int i = 0; i < 8; i++) {
            float4 xv = *(const float4*)&x_s[(rb + i) * 68 + k];  // broadcast
            gi[i][0] = fmaf(xv.x, w0.x, fmaf(xv.y, w0.y, fmaf(xv.z, w0.z, fmaf(xv.w, w0.w, gi[i][0]))));
            gi[i][1] = fmaf(xv.x, w1.x, fmaf(xv.y, w1.y, fmaf(xv.z, w1.z, fmaf(xv.w, w1.w, gi[i][1]))));
            gi[i][2] = fmaf(xv.x, w2.x, fmaf(xv.y, w2.y, fmaf(xv.z, w2.z, fmaf(xv.w, w2.w, gi[i][2]))));
        }
    }
    // gh: k = 0..31 over h part
    for (int k = 0; k < 32; k += 4) {
        float4 w0 = *(const float4*)&whh_s[e * WHH_PITCH + k];
        float4 w1 = *(const float4*)&whh_s[(32 + e) * WHH_PITCH + k];
        float4 w2 = *(const float4*)&whh_s[(64 + e) * WHH_PITCH + k];
#pragma unroll
        for (int i = 0; i < 8; i++) {
            float4 xv = *(const float4*)&x_s[(rb + i) * 68 + k];  // broadcast (h part)
            gh[i][0] = fmaf(xv.x, w0.x, fmaf(xv.y, w0.y, fmaf(xv.z, w0.z, fmaf(xv.w, w0.w, gh[i][0]))));
            gh[i][1] = fmaf(xv.x, w1.x, fmaf(xv.y, w1.y, fmaf(xv.z, w1.z, fmaf(xv.w, w1.w, gh[i][1]))));
            gh[i][2] = fmaf(xv.x, w2.x, fmaf(xv.y, w2.y, fmaf(xv.z, w2.z, fmaf(xv.w, w2.w, gh[i][2]))));
        }
    }
    float bc0 = bc[e], bc1 = bc[32 + e], bc2 = bc[64 + e];
    float bi0 = bihd[e], bi1 = bihd[32 + e], bi2 = bihd[64 + e];
    float bh0 = bhhd[e], bh1 = bhhd[32 + e], bh2 = bhhd[64 + e];
#pragma unroll
    for (int i = 0; i < 8; i++) {
        int node = row0 + rb + i;
        float hn = g_deg[node] > 0.f ? 1.f : 0.f;
        float ir = bi0 + hn * (gi[i][0] + bc0);
        float iz = bi1 + hn * (gi[i][1] + bc1);
        float in_ = bi2 + hn * (gi[i][2] + bc2);
        float rg = 1.f / (1.f + expf(-(ir + (gh[i][0] + bh0))));
        float z  = 1.f / (1.f + expf(-(iz + (gh[i][1] + bh1))));
        float n  = tanhf(in_ + rg * (gh[i][2] + bh2));
        float hp = x_s[(rb + i) * 68 + e];
        float hnew = (1.f - z) * n + z * hp;
        if (last) {
            out[(size_t)node * EMBED + e] = hnew;
            int b = bidx[node];
            atomicAdd(&g_pool_sum[b * EMBED + e], hnew);
            if (e == 0) atomicAdd(&g_pool_cnt[b], 1.0f);
        } else {
            g_h[(size_t)node * EMBED + e] = hnew;
            g_hq[(size_t)node * EMBED + e] = __float2half_rn(hnew);
        }
    }
}

__global__ void __launch_bounds__(256) k_graph(const float* __restrict__ pW,
                                               const float* __restrict__ pb,
                                               float* __restrict__ out) {
    __shared__ float mean[EMBED];
    __shared__ float Ws[EMBED * HIDDEN];
    int b = blockIdx.x;
    int t = threadIdx.x;
    for (int idx = t; idx < HIDDEN * EMBED; idx += 256) {
        int o = idx >> 5, e = idx & 31;
        Ws[e * HIDDEN + o] = pW[idx];
    }
    if (t < EMBED) {
        float cnt = g_pool_cnt[b];
        mean[t] = cnt > 0.f ? g_pool_sum[b * EMBED + t] / cnt : 0.f;
    }
    __syncthreads();
    float acc = pb[t];
#pragma unroll
    for (int e = 0; e < EMBED; e++) acc = fmaf(mean[e], Ws[e * HIDDEN + t], acc);
    out[(size_t)(N_NODES * EMBED + N_BONDS * EMBED) + b * HIDDEN + t] = acc;
}

// ---------------- launch ----------------
extern "C" void kernel_launch(void* const* d_in, const int* in_sizes, int n_in,
                              void* d_out, int out_size) {
    const int* af    = (const int*)d_in[0];
    const int* bf    = (const int*)d_in[1];
    const int* adj   = (const int*)d_in[2];
    const int* bidx  = (const int*)d_in[3];
    const float* atab = (const float*)d_in[4];
    const float* btab = (const float*)d_in[5];
    const float* msgW = (const float*)d_in[6];
    const float* msgb = (const float*)d_in[7];
    const float* Wih  = (const float*)d_in[8];
    const float* Whh  = (const float*)d_in[9];
    const float* bih  = (const float*)d_in[10];
    const float* bhh  = (const float*)d_in[11];
    const float* pW   = (const float*)d_in[12];
    const float* pb   = (const float*)d_in[13];
    float* out = (float*)d_out;

    cudaFuncSetAttribute(k_neimma, cudaFuncAttributeMaxDynamicSharedMemorySize, NEI_SMEM);
    cudaFuncSetAttribute(k_msgru, cudaFuncAttributeMaxDynamicSharedMemorySize,
                         MSGRU_SMEM_FLOATS * 4);

    k_init<<<(N_BONDS * EMBED + 255) / 256, 256>>>(af, bf, atab, btab, out);
    k_convA<<<dim3(512, 8), 256>>>(adj);
    k_compose<<<dim3(DEPTH, 4), 256>>>(msgW, msgb, Wih);
    for (int d = 0; d < DEPTH; ++d) {
        k_neimma<<<dim3(128, 4), 128, NEI_SMEM>>>();
        k_msgru<<<N_NODES / 64, 256, MSGRU_SMEM_FLOATS * 4>>>(
            d, d == DEPTH - 1, Whh, bih, bhh, bidx, out);
    }
    k_graph<<<NUM_GRAPHS, HIDDEN>>>(pW, pb, out);
}

// round 14
// speedup vs baseline: 1.0363x; 1.0363x over previous
#include <cuda_runtime.h>
#include <cuda_fp16.h>
#include <math.h>
#include <stdint.h>

#define N_NODES 8192
#define N_BONDS 16384
#define EMBED 32
#define HIDDEN 256
#define DEPTH 10
#define NUM_GRAPHS 256

// ---------------- static device scratch ----------------
// A image: 4-bit {0,1}, fragment-ordered for mma.m16n8k16.f16.
__device__ __align__(16) uint8_t g_A4[(size_t)512 * 64 * 1024];  // 32MB
__device__ __align__(16) __half g_hq[(size_t)N_NODES * EMBED];   // [j][e] fp16
__device__ __align__(16) float g_h[N_NODES * EMBED];
__device__ __align__(16) float g_neip[4][N_NODES * EMBED];       // [kq][node][e]
__device__ __align__(16) float g_Wc[DEPTH][64 * 96];             // composed, [k][g]
__device__ float g_bc[DEPTH][96];                                // Wih@msg_b
__device__ float g_deg[N_NODES];
__device__ float g_pool_sum[NUM_GRAPHS * EMBED];
__device__ float g_pool_cnt[NUM_GRAPHS];

// ---------------- PTX helpers ----------------
__device__ __forceinline__ uint32_t smem_u32(const void* p) {
    uint32_t a;
    asm("{ .reg .u64 t; cvta.to.shared.u64 t, %1; cvt.u32.u64 %0, t; }" : "=r"(a) : "l"(p));
    return a;
}
__device__ __forceinline__ uint32_t prmt0(uint32_t a, uint32_t sel) {
    uint32_t d;
    asm("prmt.b32 %0, %1, 0, %2;" : "=r"(d) : "r"(a), "r"(sel));
    return d;
}
__device__ __forceinline__ void cp16(uint32_t dst, const void* src) {
    asm volatile("cp.async.cg.shared.global [%0], [%1], 16;" :: "r"(dst), "l"(src));
}
__device__ __forceinline__ void lds128(uint4& v, uint32_t addr) {
    asm volatile("ld.shared.v4.u32 {%0,%1,%2,%3}, [%4];"
                 : "=r"(v.x), "=r"(v.y), "=r"(v.z), "=r"(v.w) : "r"(addr));
}
__device__ __forceinline__ void ldm_x4_trans(uint32_t* r, uint32_t addr) {
    asm volatile("ldmatrix.sync.aligned.m8n8.x4.trans.shared.b16 {%0,%1,%2,%3}, [%4];"
                 : "=r"(r[0]), "=r"(r[1]), "=r"(r[2]), "=r"(r[3]) : "r"(addr));
}
__device__ __forceinline__ void mma_f16(float* c, uint32_t a0, uint32_t a1,
                                        uint32_t a2, uint32_t a3,
                                        uint32_t b0, uint32_t b1) {
    asm volatile(
        "mma.sync.aligned.m16n8k16.row.col.f32.f16.f16.f32 "
        "{%0,%1,%2,%3}, {%4,%5,%6,%7}, {%8,%9}, {%0,%1,%2,%3};"
        : "+f"(c[0]), "+f"(c[1]), "+f"(c[2]), "+f"(c[3])
        : "r"(a0), "r"(a1), "r"(a2), "r"(a3), "r"(b0), "r"(b1));
}
__device__ __forceinline__ float fast_sigmoid(float x) {
    return __fdividef(1.f, 1.f + __expf(-x));
}
__device__ __forceinline__ float fast_tanh(float x) {
    float e = __expf(2.f * x);
    return __fdividef(e - 1.f, e + 1.f);
}

// ---------------- init ----------------
__global__ void k_init(const int* __restrict__ af, const int* __restrict__ bf,
                       const float* __restrict__ atab, const float* __restrict__ btab,
                       float* __restrict__ out) {
    int idx = blockIdx.x * 256 + threadIdx.x;
    if (idx < N_BONDS * EMBED)
        out[N_NODES * EMBED + idx] = btab[bf[idx >> 5] * EMBED + (idx & 31)];
    if (idx < N_NODES * EMBED) {
        float h = atab[af[idx >> 5] * EMBED + (idx & 31)];
        g_h[idx] = h;
        g_hq[idx] = __float2half_rn(h);
    }
    if (idx < N_NODES) g_deg[idx] = 0.f;
    if (idx < NUM_GRAPHS * EMBED) g_pool_sum[idx] = 0.f;
    if (idx < NUM_GRAPHS) g_pool_cnt[idx] = 0.f;
}

// ---------------- adjacency -> 4-bit fragment-ordered image + degree ----------------
__global__ void __launch_bounds__(256) k_convA(const int* __restrict__ adj) {
    int t = threadIdx.x, lane = t & 31, w = t >> 5;
    int mb = blockIdx.x;
    int kc = blockIdx.y * 8 + w;
    int r = lane >> 2, kq = (lane & 3) * 2;
    int row0 = mb * 16;
    uint8_t* dst = g_A4 + (((size_t)mb * 64 + kc) * 1024) + (size_t)lane * 32;
    int cnt0 = 0, cnt8 = 0;
    uint32_t wv[8];
#pragma unroll
    for (int kt = 0; kt < 8; kt++) {
        int k0 = kc * 128 + kt * 16 + kq;
        int2 p00 = *(const int2*)&adj[(size_t)(row0 + r) * N_NODES + k0];
        int2 p08 = *(const int2*)&adj[(size_t)(row0 + r) * N_NODES + k0 + 8];
        int2 p80 = *(const int2*)&adj[(size_t)(row0 + r + 8) * N_NODES + k0];
        int2 p88 = *(const int2*)&adj[(size_t)(row0 + r + 8) * N_NODES + k0 + 8];
        uint32_t b0 = (p00.x != 0), b1 = (p00.y != 0);
        uint32_t b2 = (p08.x != 0), b3 = (p08.y != 0);
        uint32_t c0 = (p80.x != 0), c1 = (p80.y != 0);
        uint32_t c2 = (p88.x != 0), c3 = (p88.y != 0);
        cnt0 += b0 + b1 + b2 + b3;
        cnt8 += c0 + c1 + c2 + c3;
        wv[kt] = b0 | (c0 << 4) | (b1 << 8) | (c1 << 12) |
                 (b2 << 16) | (c2 << 20) | (b3 << 24) | (c3 << 28);
    }
    *(uint4*)(dst) = make_uint4(wv[0], wv[1], wv[2], wv[3]);
    *(uint4*)(dst + 16) = make_uint4(wv[4], wv[5], wv[6], wv[7]);
    cnt0 += __shfl_down_sync(0xffffffffu, cnt0, 2, 4);
    cnt0 += __shfl_down_sync(0xffffffffu, cnt0, 1, 4);
    cnt8 += __shfl_down_sync(0xffffffffu, cnt8, 2, 4);
    cnt8 += __shfl_down_sync(0xffffffffu, cnt8, 1, 4);
    if ((lane & 3) == 0) {
        atomicAdd(&g_deg[row0 + r], (float)cnt0);
        atomicAdd(&g_deg[row0 + r + 8], (float)cnt8);
    }
}

// ---------------- compose W_c = Wih @ Wmsg ([k][96] layout) ----------
__global__ void __launch_bounds__(256) k_composeW(const float* __restrict__ msgW,
                                                  const float* __restrict__ Wih) {
    int d = blockIdx.x, q = blockIdx.y;
    int t = threadIdx.x;
    const float* Wd = msgW + (size_t)d * 256 * 64;
    const float* Wi = Wih + (size_t)d * 96 * 256;
    for (int idx = t; idx < 24 * 64; idx += 256) {
        int g = q * 24 + (idx >> 6), e = idx & 63;
        float acc = 0.f;
#pragma unroll 4
        for (int k = 0; k < 256; k++) acc = fmaf(Wi[g * 256 + k], Wd[k * 64 + e], acc);
        g_Wc[d][e * 96 + g] = acc;  // [k=e][g]
    }
}
__global__ void __launch_bounds__(96) k_composeB(const float* __restrict__ msgb,
                                                 const float* __restrict__ Wih) {
    int d = blockIdx.x;
    int t = threadIdx.x;
    const float* Wi = Wih + (size_t)d * 96 * 256;
    float acc = 0.f;
    for (int k = 0; k < 256; k++) acc = fmaf(Wi[t * 256 + k], msgb[d * 256 + k], acc);
    g_bc[d][t] = acc;
}

// ---------------- nei partials = A @ h_fp16 via mma.sync f16 (R12 version) ----------
#define NEI_PITCH 80
#define NEI_STAGE 14336
#define NEI_SMEM (4 * NEI_STAGE)
#define NEI_CHUNKS 16
#define NIBM 0x0F0F0F0Fu
__global__ void __launch_bounds__(128, 4) k_neimma() {
    extern __shared__ uint8_t smem[];
    uint32_t sb = smem_u32(smem);
    int t = threadIdx.x, lane = t & 31, w = t >> 5;
    int mtile = blockIdx.x, kq = blockIdx.y;

    const uint8_t* Bbase = (const uint8_t*)g_hq + (size_t)kq * 2048 * 64;
    int apiece = t >> 5, aoff = (t & 31) * 32;
    const uint8_t* Asrc = g_A4 +
        ((size_t)((mtile * 4 + apiece) * 64 + kq * 16)) * 1024 + aoff;

#define LOADAB(c, s)                                                            \
    {                                                                           \
        uint32_t dst = sb + (s) * NEI_STAGE;                                    \
        cp16(dst + apiece * 1024 + aoff, Asrc + (size_t)(c) * 1024);            \
        cp16(dst + apiece * 1024 + aoff + 16, Asrc + (size_t)(c) * 1024 + 16);  \
        uint32_t dstb = dst + 4096;                                             \
        const uint8_t* srcb = Bbase + (size_t)(c) * 128 * 64;                   \
        _Pragma("unroll")                                                       \
        for (int i = 0; i < 4; i++) {                                           \
            int idx = t + i * 128;                                              \
            int row = idx >> 2, cg = idx & 3;                                   \
            cp16(dstb + row * NEI_PITCH + cg * 16, srcb + row * 64 + cg * 16);  \
        }                                                                       \
        asm volatile("cp.async.commit_group;");                                 \
    }

    LOADAB(0, 0);
    LOADAB(1, 1);
    LOADAB(2, 2);

    float acc[4][4];
#pragma unroll
    for (int p = 0; p < 4; p++)
#pragma unroll
        for (int i = 0; i < 4; i++) acc[p][i] = 0.f;

    int krb = lane & 15;
    int chi = lane >> 4;
    uint32_t aaddr_base = (uint32_t)(w * 1024 + lane * 32);
    uint32_t boff0 = (uint32_t)chi * 16;
    uint32_t boff1 = 32 + (uint32_t)chi * 16;

    for (int c = 0; c < NEI_CHUNKS; c++) {
        asm volatile("cp.async.wait_group 2;");
        __syncthreads();
        if (c + 3 < NEI_CHUNKS) LOADAB(c + 3, (c + 3) & 3);
        uint32_t sbase = sb + (c & 3) * NEI_STAGE;
        uint4 aw0, aw1;
        lds128(aw0, sbase + aaddr_base);
        lds128(aw1, sbase + aaddr_base + 16);
        uint32_t bb = sbase + 4096;

        uint32_t bf_cur[2][4], bf_nxt[2][4];
        {
            uint32_t rowaddr = bb + (uint32_t)krb * NEI_PITCH;
            ldm_x4_trans(bf_cur[0], rowaddr + boff0);
            ldm_x4_trans(bf_cur[1], rowaddr + boff1);
        }
#pragma unroll
        for (int kt = 0; kt < 8; kt++) {
            if (kt < 7) {
                uint32_t rowaddr = bb + (uint32_t)((kt + 1) * 16 + krb) * NEI_PITCH;
                ldm_x4_trans(bf_nxt[0], rowaddr + boff0);
                ldm_x4_trans(bf_nxt[1], rowaddr + boff1);
            }
            uint4 q = (kt & 4) ? aw1 : aw0;
            uint32_t wv = (kt & 2) ? ((kt & 1) ? q.w : q.z) : ((kt & 1) ? q.y : q.x);
            uint32_t lo = wv & NIBM;
            uint32_t hi = (wv >> 4) & NIBM;
            uint32_t a0 = prmt0(lo, 0x4140) * 0x3C00u;
            uint32_t a2 = prmt0(lo, 0x4342) * 0x3C00u;
            uint32_t a1 = prmt0(hi, 0x4140) * 0x3C00u;
            uint32_t a3 = prmt0(hi, 0x4342) * 0x3C00u;
            mma_f16(acc[0], a0, a1, a2, a3, bf_cur[0][0], bf_cur[0][1]);
            mma_f16(acc[1], a0, a1, a2, a3, bf_cur[0][2], bf_cur[0][3]);
            mma_f16(acc[2], a0, a1, a2, a3, bf_cur[1][0], bf_cur[1][1]);
            mma_f16(acc[3], a0, a1, a2, a3, bf_cur[1][2], bf_cur[1][3]);
            if (kt < 7) {
#pragma unroll
                for (int p = 0; p < 2; p++)
#pragma unroll
                    for (int i = 0; i < 4; i++) bf_cur[p][i] = bf_nxt[p][i];
            }
        }
    }

    float* base = g_neip[kq];
    int r = lane >> 2, c0 = (lane & 3) * 2;
    int node0 = mtile * 64 + w * 16 + r;
#pragma unroll
    for (int p = 0; p < 4; p++) {
        int col = p * 8 + c0;
        *(float2*)&base[(size_t)node0 * 32 + col] = make_float2(acc[p][0], acc[p][1]);
        *(float2*)&base[(size_t)(node0 + 8) * 32 + col] = make_float2(acc[p][2], acc[p][3]);
    }
#undef LOADAB
}

// ---------------- fused (composed msg+GRU), R10 config + fast gates ----------
// 32 nodes/block, 256 blocks.
#define MSGRU_SMEM_FLOATS (32 * 68 + 64 * 96 + 32 * 96)
__global__ void __launch_bounds__(256) k_msgru(int d, int last,
                                               const float* __restrict__ Whh,
                                               const float* __restrict__ bih,
                                               const float* __restrict__ bhh,
                                               const int* __restrict__ bidx,
                                               float* __restrict__ out) {
    extern __shared__ float sm[];
    float* x_s = sm;                   // [32 nodes][68] : h(32) | nei_mean(32)
    float* wc_s = x_s + 32 * 68;       // [k=64][96]
    float* whh_s = wc_s + 64 * 96;     // [k=32][96]
    int row0 = blockIdx.x * 32;
    int t = threadIdx.x;
    const float* Wc = g_Wc[d];
    const float* bc = g_bc[d];
    const float* bihd = bih + d * 96;
    const float* bhhd = bhh + d * 96;
    const float* Whhd = Whh + (size_t)d * 96 * 32;

    for (int idx = t; idx < 32 * EMBED; idx += 256) {
        int r = idx >> 5, e = idx & 31;
        int node = row0 + r;
        float invd = 1.0f / fmaxf(g_deg[node], 1.0f);
        int o = node * 32 + e;
        float s = g_neip[0][o] + g_neip[1][o] + g_neip[2][o] + g_neip[3][o];
        x_s[r * 68 + e] = g_h[o];
        x_s[r * 68 + 32 + e] = s * invd;
    }
    for (int idx = t; idx < 64 * 96; idx += 256) wc_s[idx] = Wc[idx];
    for (int idx = t; idx < 96 * EMBED; idx += 256) {
        int g = idx >> 5, k = idx & 31;
        whh_s[k * 96 + g] = Whhd[idx];
    }
    __syncthreads();

    int e = t & 31;
    int rb = (t >> 5) * 4;
    float gi[4][3], gh[4][3];
#pragma unroll
    for (int i = 0; i < 4; i++) {
        gi[i][0] = gi[i][1] = gi[i][2] = 0.f;
        gh[i][0] = gh[i][1] = gh[i][2] = 0.f;
    }
    for (int k = 0; k < 64; k++) {
        float w0 = wc_s[k * 96 + e];
        float w1 = wc_s[k * 96 + 32 + e];
        float w2 = wc_s[k * 96 + 64 + e];
#pragma unroll
        for (int i = 0; i < 4; i++) {
            float x = x_s[(rb + i) * 68 + k];
            gi[i][0] = fmaf(x, w0, gi[i][0]);
            gi[i][1] = fmaf(x, w1, gi[i][1]);
            gi[i][2] = fmaf(x, w2, gi[i][2]);
        }
    }
    for (int k = 0; k < EMBED; k++) {
        float w0 = whh_s[k * 96 + e];
        float w1 = whh_s[k * 96 + 32 + e];
        float w2 = whh_s[k * 96 + 64 + e];
#pragma unroll
        for (int i = 0; i < 4; i++) {
            float hv = x_s[(rb + i) * 68 + k];
            gh[i][0] = fmaf(hv, w0, gh[i][0]);
            gh[i][1] = fmaf(hv, w1, gh[i][1]);
            gh[i][2] = fmaf(hv, w2, gh[i][2]);
        }
    }
    float bc0 = bc[e], bc1 = bc[32 + e], bc2 = bc[64 + e];
    float bi0 = bihd[e], bi1 = bihd[32 + e], bi2 = bihd[64 + e];
    float bh0 = bhhd[e], bh1 = bhhd[32 + e], bh2 = bhhd[64 + e];
#pragma unroll
    for (int i = 0; i < 4; i++) {
        int node = row0 + rb + i;
        float hn = g_deg[node] > 0.f ? 1.f : 0.f;
        float ir = bi0 + hn * (gi[i][0] + bc0);
        float iz = bi1 + hn * (gi[i][1] + bc1);
        float in_ = bi2 + hn * (gi[i][2] + bc2);
        float rg = fast_sigmoid(ir + (gh[i][0] + bh0));
        float z  = fast_sigmoid(iz + (gh[i][1] + bh1));
        float n  = fast_tanh(in_ + rg * (gh[i][2] + bh2));
        float hp = x_s[(rb + i) * 68 + e];
        float hnew = (1.f - z) * n + z * hp;
        if (last) {
            out[(size_t)node * EMBED + e] = hnew;
            int b = bidx[node];
            atomicAdd(&g_pool_sum[b * EMBED + e], hnew);
            if (e == 0) atomicAdd(&g_pool_cnt[b], 1.0f);
        } else {
            g_h[(size_t)node * EMBED + e] = hnew;
            g_hq[(size_t)node * EMBED + e] = __float2half_rn(hnew);
        }
    }
}

__global__ void __launch_bounds__(256) k_graph(const float* __restrict__ pW,
                                               const float* __restrict__ pb,
                                               float* __restrict__ out) {
    __shared__ float mean[EMBED];
    __shared__ float Ws[EMBED * HIDDEN];
    int b = blockIdx.x;
    int t = threadIdx.x;
    for (int idx = t; idx < HIDDEN * EMBED; idx += 256) {
        int o = idx >> 5, e = idx & 31;
        Ws[e * HIDDEN + o] = pW[idx];
    }
    if (t < EMBED) {
        float cnt = g_pool_cnt[b];
        mean[t] = cnt > 0.f ? g_pool_sum[b * EMBED + t] / cnt : 0.f;
    }
    __syncthreads();
    float acc = pb[t];
#pragma unroll
    for (int e = 0; e < EMBED; e++) acc = fmaf(mean[e], Ws[e * HIDDEN + t], acc);
    out[(size_t)(N_NODES * EMBED + N_BONDS * EMBED) + b * HIDDEN + t] = acc;
}

// ---------------- launch ----------------
extern "C" void kernel_launch(void* const* d_in, const int* in_sizes, int n_in,
                              void* d_out, int out_size) {
    const int* af    = (const int*)d_in[0];
    const int* bf    = (const int*)d_in[1];
    const int* adj   = (const int*)d_in[2];
    const int* bidx  = (const int*)d_in[3];
    const float* atab = (const float*)d_in[4];
    const float* btab = (const float*)d_in[5];
    const float* msgW = (const float*)d_in[6];
    const float* msgb = (const float*)d_in[7];
    const float* Wih  = (const float*)d_in[8];
    const float* Whh  = (const float*)d_in[9];
    const float* bih  = (const float*)d_in[10];
    const float* bhh  = (const float*)d_in[11];
    const float* pW   = (const float*)d_in[12];
    const float* pb   = (const float*)d_in[13];
    float* out = (float*)d_out;

    cudaFuncSetAttribute(k_neimma, cudaFuncAttributeMaxDynamicSharedMemorySize, NEI_SMEM);
    cudaFuncSetAttribute(k_msgru, cudaFuncAttributeMaxDynamicSharedMemorySize,
                         MSGRU_SMEM_FLOATS * 4);

    // launch order chosen so ncu's "-s 5 -c 1" captures k_msgru (launch #6)
    k_init<<<(N_BONDS * EMBED + 255) / 256, 256>>>(af, bf, atab, btab, out);      // 1
    k_convA<<<dim3(512, 8), 256>>>(adj);                                           // 2
    k_composeW<<<dim3(DEPTH, 4), 256>>>(msgW, Wih);                                // 3
    k_composeB<<<DEPTH, 96>>>(msgb, Wih);                                          // 4
    for (int d = 0; d < DEPTH; ++d) {
        k_neimma<<<dim3(128, 4), 128, NEI_SMEM>>>();                               // 5, 7, ...
        k_msgru<<<N_NODES / 32, 256, MSGRU_SMEM_FLOATS * 4>>>(
            d, d == DEPTH - 1, Whh, bih, bhh, bidx, out);                          // 6 <- captured
    }
    k_graph<<<NUM_GRAPHS, HIDDEN>>>(pW, pb, out);
}

// round 15
// speedup vs baseline: 1.1952x; 1.1534x over previous
#include <cuda_runtime.h>
#include <cuda_fp16.h>
#include <math.h>
#include <stdint.h>

#define N_NODES 8192
#define N_BONDS 16384
#define EMBED 32
#define HIDDEN 256
#define DEPTH 10
#define NUM_GRAPHS 256

// ---------------- static device scratch ----------------
// A image: 4-bit {0,1}, fragment-ordered for mma.m16n8k16.f16.
__device__ __align__(16) uint8_t g_A4[(size_t)512 * 64 * 1024];  // 32MB
__device__ __align__(16) __half g_hq[(size_t)N_NODES * EMBED];   // [j][e] fp16
__device__ __align__(16) float g_h[N_NODES * EMBED];
__device__ __align__(16) float g_neip[4][N_NODES * EMBED];       // [kq][node][e]
__device__ __align__(16) float g_Wc[DEPTH][64 * 96];             // composed, [k][g]
__device__ float g_bc[DEPTH][96];                                // Wih@msg_b
__device__ float g_deg[N_NODES];
__device__ float g_pool_sum[NUM_GRAPHS * EMBED];
__device__ float g_pool_cnt[NUM_GRAPHS];

// ---------------- PTX helpers ----------------
__device__ __forceinline__ uint32_t smem_u32(const void* p) {
    uint32_t a;
    asm("{ .reg .u64 t; cvta.to.shared.u64 t, %1; cvt.u32.u64 %0, t; }" : "=r"(a) : "l"(p));
    return a;
}
__device__ __forceinline__ uint32_t prmt0(uint32_t a, uint32_t sel) {
    uint32_t d;
    asm("prmt.b32 %0, %1, 0, %2;" : "=r"(d) : "r"(a), "r"(sel));
    return d;
}
__device__ __forceinline__ void cp16(uint32_t dst, const void* src) {
    asm volatile("cp.async.cg.shared.global [%0], [%1], 16;" :: "r"(dst), "l"(src));
}
__device__ __forceinline__ void lds128(uint4& v, uint32_t addr) {
    asm volatile("ld.shared.v4.u32 {%0,%1,%2,%3}, [%4];"
                 : "=r"(v.x), "=r"(v.y), "=r"(v.z), "=r"(v.w) : "r"(addr));
}
__device__ __forceinline__ void ldm_x4_trans(uint32_t* r, uint32_t addr) {
    asm volatile("ldmatrix.sync.aligned.m8n8.x4.trans.shared.b16 {%0,%1,%2,%3}, [%4];"
                 : "=r"(r[0]), "=r"(r[1]), "=r"(r[2]), "=r"(r[3]) : "r"(addr));
}
__device__ __forceinline__ void mma_f16(float* c, uint32_t a0, uint32_t a1,
                                        uint32_t a2, uint32_t a3,
                                        uint32_t b0, uint32_t b1) {
    asm volatile(
        "mma.sync.aligned.m16n8k16.row.col.f32.f16.f16.f32 "
        "{%0,%1,%2,%3}, {%4,%5,%6,%7}, {%8,%9}, {%0,%1,%2,%3};"
        : "+f"(c[0]), "+f"(c[1]), "+f"(c[2]), "+f"(c[3])
        : "r"(a0), "r"(a1), "r"(a2), "r"(a3), "r"(b0), "r"(b1));
}
__device__ __forceinline__ float fast_sigmoid(float x) {
    return __fdividef(1.f, 1.f + __expf(-x));
}
__device__ __forceinline__ float fast_tanh(float x) {
    float e = __expf(2.f * x);
    return __fdividef(e - 1.f, e + 1.f);
}

// ---------------- fused init + compose ----------------
// blocks 0..2047: init (bond emb, h, hq, zero accumulators)
// blocks 2048..3007: compose (d, g) -> Wc row [64] + bc[g]
#define SETUP_INIT_BLOCKS 2048
__global__ void __launch_bounds__(256) k_setup(
    const int* __restrict__ af, const int* __restrict__ bf,
    const float* __restrict__ atab, const float* __restrict__ btab,
    const float* __restrict__ msgW, const float* __restrict__ msgb,
    const float* __restrict__ Wih, float* __restrict__ out) {
    int b = blockIdx.x;
    int t = threadIdx.x;
    if (b < SETUP_INIT_BLOCKS) {
        int idx = b * 256 + t;
        if (idx < N_BONDS * EMBED)
            out[N_NODES * EMBED + idx] = btab[bf[idx >> 5] * EMBED + (idx & 31)];
        if (idx < N_NODES * EMBED) {
            float h = atab[af[idx >> 5] * EMBED + (idx & 31)];
            g_h[idx] = h;
            g_hq[idx] = __float2half_rn(h);
        }
        if (idx < N_NODES) g_deg[idx] = 0.f;
        if (idx < NUM_GRAPHS * EMBED) g_pool_sum[idx] = 0.f;
        if (idx < NUM_GRAPHS) g_pool_cnt[idx] = 0.f;
    } else {
        int db = b - SETUP_INIT_BLOCKS;
        int d = db / 96, g = db % 96;
        __shared__ float wi_s[256];
        wi_s[t] = Wih[((size_t)d * 96 + g) * 256 + t];
        __syncthreads();
        if (t < 64) {
            const float* Wd = msgW + (size_t)d * 256 * 64 + t;
            float acc = 0.f;
#pragma unroll 8
            for (int k = 0; k < 256; k++) acc = fmaf(wi_s[k], Wd[(size_t)k * 64], acc);
            g_Wc[d][t * 96 + g] = acc;  // [k=t][g]
        } else if (t < 96) {
            int j = t - 64;
            const float* mb = msgb + d * 256 + j * 8;
            float acc = 0.f;
#pragma unroll
            for (int kk = 0; kk < 8; kk++) acc = fmaf(wi_s[j * 8 + kk], mb[kk], acc);
#pragma unroll
            for (int off = 16; off; off >>= 1)
                acc += __shfl_down_sync(0xffffffffu, acc, off);
            if (j == 0) g_bc[d][g] = acc;
        }
    }
}

// ---------------- adjacency -> 4-bit fragment-ordered image + degree ----------------
__global__ void __launch_bounds__(256) k_convA(const int* __restrict__ adj) {
    int t = threadIdx.x, lane = t & 31, w = t >> 5;
    int mb = blockIdx.x;
    int kc = blockIdx.y * 8 + w;
    int r = lane >> 2, kq = (lane & 3) * 2;
    int row0 = mb * 16;
    uint8_t* dst = g_A4 + (((size_t)mb * 64 + kc) * 1024) + (size_t)lane * 32;
    int cnt0 = 0, cnt8 = 0;
    uint32_t wv[8];
#pragma unroll
    for (int kt = 0; kt < 8; kt++) {
        int k0 = kc * 128 + kt * 16 + kq;
        int2 p00 = *(const int2*)&adj[(size_t)(row0 + r) * N_NODES + k0];
        int2 p08 = *(const int2*)&adj[(size_t)(row0 + r) * N_NODES + k0 + 8];
        int2 p80 = *(const int2*)&adj[(size_t)(row0 + r + 8) * N_NODES + k0];
        int2 p88 = *(const int2*)&adj[(size_t)(row0 + r + 8) * N_NODES + k0 + 8];
        uint32_t b0 = (p00.x != 0), b1 = (p00.y != 0);
        uint32_t b2 = (p08.x != 0), b3 = (p08.y != 0);
        uint32_t c0 = (p80.x != 0), c1 = (p80.y != 0);
        uint32_t c2 = (p88.x != 0), c3 = (p88.y != 0);
        cnt0 += b0 + b1 + b2 + b3;
        cnt8 += c0 + c1 + c2 + c3;
        wv[kt] = b0 | (c0 << 4) | (b1 << 8) | (c1 << 12) |
                 (b2 << 16) | (c2 << 20) | (b3 << 24) | (c3 << 28);
    }
    *(uint4*)(dst) = make_uint4(wv[0], wv[1], wv[2], wv[3]);
    *(uint4*)(dst + 16) = make_uint4(wv[4], wv[5], wv[6], wv[7]);
    cnt0 += __shfl_down_sync(0xffffffffu, cnt0, 2, 4);
    cnt0 += __shfl_down_sync(0xffffffffu, cnt0, 1, 4);
    cnt8 += __shfl_down_sync(0xffffffffu, cnt8, 2, 4);
    cnt8 += __shfl_down_sync(0xffffffffu, cnt8, 1, 4);
    if ((lane & 3) == 0) {
        atomicAdd(&g_deg[row0 + r], (float)cnt0);
        atomicAdd(&g_deg[row0 + r + 8], (float)cnt8);
    }
}

// ---------------- nei partials = A @ h_fp16 via mma.sync f16 (R12 version) ----------
#define NEI_PITCH 80
#define NEI_STAGE 14336
#define NEI_SMEM (4 * NEI_STAGE)
#define NEI_CHUNKS 16
#define NIBM 0x0F0F0F0Fu
__global__ void __launch_bounds__(128, 4) k_neimma() {
    extern __shared__ uint8_t smem[];
    uint32_t sb = smem_u32(smem);
    int t = threadIdx.x, lane = t & 31, w = t >> 5;
    int mtile = blockIdx.x, kq = blockIdx.y;

    const uint8_t* Bbase = (const uint8_t*)g_hq + (size_t)kq * 2048 * 64;
    int apiece = t >> 5, aoff = (t & 31) * 32;
    const uint8_t* Asrc = g_A4 +
        ((size_t)((mtile * 4 + apiece) * 64 + kq * 16)) * 1024 + aoff;

#define LOADAB(c, s)                                                            \
    {                                                                           \
        uint32_t dst = sb + (s) * NEI_STAGE;                                    \
        cp16(dst + apiece * 1024 + aoff, Asrc + (size_t)(c) * 1024);            \
        cp16(dst + apiece * 1024 + aoff + 16, Asrc + (size_t)(c) * 1024 + 16);  \
        uint32_t dstb = dst + 4096;                                             \
        const uint8_t* srcb = Bbase + (size_t)(c) * 128 * 64;                   \
        _Pragma("unroll")                                                       \
        for (int i = 0; i < 4; i++) {                                           \
            int idx = t + i * 128;                                              \
            int row = idx >> 2, cg = idx & 3;                                   \
            cp16(dstb + row * NEI_PITCH + cg * 16, srcb + row * 64 + cg * 16);  \
        }                                                                       \
        asm volatile("cp.async.commit_group;");                                 \
    }

    LOADAB(0, 0);
    LOADAB(1, 1);
    LOADAB(2, 2);

    float acc[4][4];
#pragma unroll
    for (int p = 0; p < 4; p++)
#pragma unroll
        for (int i = 0; i < 4; i++) acc[p][i] = 0.f;

    int krb = lane & 15;
    int chi = lane >> 4;
    uint32_t aaddr_base = (uint32_t)(w * 1024 + lane * 32);
    uint32_t boff0 = (uint32_t)chi * 16;
    uint32_t boff1 = 32 + (uint32_t)chi * 16;

    for (int c = 0; c < NEI_CHUNKS; c++) {
        asm volatile("cp.async.wait_group 2;");
        __syncthreads();
        if (c + 3 < NEI_CHUNKS) LOADAB(c + 3, (c + 3) & 3);
        uint32_t sbase = sb + (c & 3) * NEI_STAGE;
        uint4 aw0, aw1;
        lds128(aw0, sbase + aaddr_base);
        lds128(aw1, sbase + aaddr_base + 16);
        uint32_t bb = sbase + 4096;

        uint32_t bf_cur[2][4], bf_nxt[2][4];
        {
            uint32_t rowaddr = bb + (uint32_t)krb * NEI_PITCH;
            ldm_x4_trans(bf_cur[0], rowaddr + boff0);
            ldm_x4_trans(bf_cur[1], rowaddr + boff1);
        }
#pragma unroll
        for (int kt = 0; kt < 8; kt++) {
            if (kt < 7) {
                uint32_t rowaddr = bb + (uint32_t)((kt + 1) * 16 + krb) * NEI_PITCH;
                ldm_x4_trans(bf_nxt[0], rowaddr + boff0);
                ldm_x4_trans(bf_nxt[1], rowaddr + boff1);
            }
            uint4 q = (kt & 4) ? aw1 : aw0;
            uint32_t wv = (kt & 2) ? ((kt & 1) ? q.w : q.z) : ((kt & 1) ? q.y : q.x);
            uint32_t lo = wv & NIBM;
            uint32_t hi = (wv >> 4) & NIBM;
            uint32_t a0 = prmt0(lo, 0x4140) * 0x3C00u;
            uint32_t a2 = prmt0(lo, 0x4342) * 0x3C00u;
            uint32_t a1 = prmt0(hi, 0x4140) * 0x3C00u;
            uint32_t a3 = prmt0(hi, 0x4342) * 0x3C00u;
            mma_f16(acc[0], a0, a1, a2, a3, bf_cur[0][0], bf_cur[0][1]);
            mma_f16(acc[1], a0, a1, a2, a3, bf_cur[0][2], bf_cur[0][3]);
            mma_f16(acc[2], a0, a1, a2, a3, bf_cur[1][0], bf_cur[1][1]);
            mma_f16(acc[3], a0, a1, a2, a3, bf_cur[1][2], bf_cur[1][3]);
            if (kt < 7) {
#pragma unroll
                for (int p = 0; p < 2; p++)
#pragma unroll
                    for (int i = 0; i < 4; i++) bf_cur[p][i] = bf_nxt[p][i];
            }
        }
    }

    float* base = g_neip[kq];
    int r = lane >> 2, c0 = (lane & 3) * 2;
    int node0 = mtile * 64 + w * 16 + r;
#pragma unroll
    for (int p = 0; p < 4; p++) {
        int col = p * 8 + c0;
        *(float2*)&base[(size_t)node0 * 32 + col] = make_float2(acc[p][0], acc[p][1]);
        *(float2*)&base[(size_t)(node0 + 8) * 32 + col] = make_float2(acc[p][2], acc[p][3]);
    }
#undef LOADAB
}

// ---------------- fused (composed msg+GRU), R10 config + fast gates ----------
// 32 nodes/block, 256 blocks.
#define MSGRU_SMEM_FLOATS (32 * 68 + 64 * 96 + 32 * 96)
__global__ void __launch_bounds__(256) k_msgru(int d, int last,
                                               const float* __restrict__ Whh,
                                               const float* __restrict__ bih,
                                               const float* __restrict__ bhh,
                                               const int* __restrict__ bidx,
                                               float* __restrict__ out) {
    extern __shared__ float sm[];
    float* x_s = sm;                   // [32 nodes][68] : h(32) | nei_mean(32)
    float* wc_s = x_s + 32 * 68;       // [k=64][96]
    float* whh_s = wc_s + 64 * 96;     // [k=32][96]
    int row0 = blockIdx.x * 32;
    int t = threadIdx.x;
    const float* Wc = g_Wc[d];
    const float* bc = g_bc[d];
    const float* bihd = bih + d * 96;
    const float* bhhd = bhh + d * 96;
    const float* Whhd = Whh + (size_t)d * 96 * 32;

    for (int idx = t; idx < 32 * EMBED; idx += 256) {
        int r = idx >> 5, e = idx & 31;
        int node = row0 + r;
        float invd = 1.0f / fmaxf(g_deg[node], 1.0f);
        int o = node * 32 + e;
        float s = g_neip[0][o] + g_neip[1][o] + g_neip[2][o] + g_neip[3][o];
        x_s[r * 68 + e] = g_h[o];
        x_s[r * 68 + 32 + e] = s * invd;
    }
    for (int idx = t; idx < 64 * 96; idx += 256) wc_s[idx] = Wc[idx];
    for (int idx = t; idx < 96 * EMBED; idx += 256) {
        int g = idx >> 5, k = idx & 31;
        whh_s[k * 96 + g] = Whhd[idx];
    }
    __syncthreads();

    int e = t & 31;
    int rb = (t >> 5) * 4;
    float gi[4][3], gh[4][3];
#pragma unroll
    for (int i = 0; i < 4; i++) {
        gi[i][0] = gi[i][1] = gi[i][2] = 0.f;
        gh[i][0] = gh[i][1] = gh[i][2] = 0.f;
    }
    for (int k = 0; k < 64; k++) {
        float w0 = wc_s[k * 96 + e];
        float w1 = wc_s[k * 96 + 32 + e];
        float w2 = wc_s[k * 96 + 64 + e];
#pragma unroll
        for (int i = 0; i < 4; i++) {
            float x = x_s[(rb + i) * 68 + k];
            gi[i][0] = fmaf(x, w0, gi[i][0]);
            gi[i][1] = fmaf(x, w1, gi[i][1]);
            gi[i][2] = fmaf(x, w2, gi[i][2]);
        }
    }
    for (int k = 0; k < EMBED; k++) {
        float w0 = whh_s[k * 96 + e];
        float w1 = whh_s[k * 96 + 32 + e];
        float w2 = whh_s[k * 96 + 64 + e];
#pragma unroll
        for (int i = 0; i < 4; i++) {
            float hv = x_s[(rb + i) * 68 + k];
            gh[i][0] = fmaf(hv, w0, gh[i][0]);
            gh[i][1] = fmaf(hv, w1, gh[i][1]);
            gh[i][2] = fmaf(hv, w2, gh[i][2]);
        }
    }
    float bc0 = bc[e], bc1 = bc[32 + e], bc2 = bc[64 + e];
    float bi0 = bihd[e], bi1 = bihd[32 + e], bi2 = bihd[64 + e];
    float bh0 = bhhd[e], bh1 = bhhd[32 + e], bh2 = bhhd[64 + e];
#pragma unroll
    for (int i = 0; i < 4; i++) {
        int node = row0 + rb + i;
        float hn = g_deg[node] > 0.f ? 1.f : 0.f;
        float ir = bi0 + hn * (gi[i][0] + bc0);
        float iz = bi1 + hn * (gi[i][1] + bc1);
        float in_ = bi2 + hn * (gi[i][2] + bc2);
        float rg = fast_sigmoid(ir + (gh[i][0] + bh0));
        float z  = fast_sigmoid(iz + (gh[i][1] + bh1));
        float n  = fast_tanh(in_ + rg * (gh[i][2] + bh2));
        float hp = x_s[(rb + i) * 68 + e];
        float hnew = (1.f - z) * n + z * hp;
        if (last) {
            out[(size_t)node * EMBED + e] = hnew;
            int b = bidx[node];
            atomicAdd(&g_pool_sum[b * EMBED + e], hnew);
            if (e == 0) atomicAdd(&g_pool_cnt[b], 1.0f);
        } else {
            g_h[(size_t)node * EMBED + e] = hnew;
            g_hq[(size_t)node * EMBED + e] = __float2half_rn(hnew);
        }
    }
}

__global__ void __launch_bounds__(256) k_graph(const float* __restrict__ pW,
                                               const float* __restrict__ pb,
                                               float* __restrict__ out) {
    __shared__ float mean[EMBED];
    __shared__ float Ws[EMBED * HIDDEN];
    int b = blockIdx.x;
    int t = threadIdx.x;
    for (int idx = t; idx < HIDDEN * EMBED; idx += 256) {
        int o = idx >> 5, e = idx & 31;
        Ws[e * HIDDEN + o] = pW[idx];
    }
    if (t < EMBED) {
        float cnt = g_pool_cnt[b];
        mean[t] = cnt > 0.f ? g_pool_sum[b * EMBED + t] / cnt : 0.f;
    }
    __syncthreads();
    float acc = pb[t];
#pragma unroll
    for (int e = 0; e < EMBED; e++) acc = fmaf(mean[e], Ws[e * HIDDEN + t], acc);
    out[(size_t)(N_NODES * EMBED + N_BONDS * EMBED) + b * HIDDEN + t] = acc;
}

// ---------------- launch ----------------
extern "C" void kernel_launch(void* const* d_in, const int* in_sizes, int n_in,
                              void* d_out, int out_size) {
    const int* af    = (const int*)d_in[0];
    const int* bf    = (const int*)d_in[1];
    const int* adj   = (const int*)d_in[2];
    const int* bidx  = (const int*)d_in[3];
    const float* atab = (const float*)d_in[4];
    const float* btab = (const float*)d_in[5];
    const float* msgW = (const float*)d_in[6];
    const float* msgb = (const float*)d_in[7];
    const float* Wih  = (const float*)d_in[8];
    const float* Whh  = (const float*)d_in[9];
    const float* bih  = (const float*)d_in[10];
    const float* bhh  = (const float*)d_in[11];
    const float* pW   = (const float*)d_in[12];
    const float* pb   = (const float*)d_in[13];
    float* out = (float*)d_out;

    cudaFuncSetAttribute(k_neimma, cudaFuncAttributeMaxDynamicSharedMemorySize, NEI_SMEM);
    cudaFuncSetAttribute(k_msgru, cudaFuncAttributeMaxDynamicSharedMemorySize,
                         MSGRU_SMEM_FLOATS * 4);

    // order: setup(1), convA(2), neimma(3), msgru(4) <- capture slot
    k_setup<<<SETUP_INIT_BLOCKS + DEPTH * 96, 256>>>(af, bf, atab, btab,
                                                     msgW, msgb, Wih, out);
    k_convA<<<dim3(512, 8), 256>>>(adj);
    for (int d = 0; d < DEPTH; ++d) {
        k_neimma<<<dim3(128, 4), 128, NEI_SMEM>>>();
        k_msgru<<<N_NODES / 32, 256, MSGRU_SMEM_FLOATS * 4>>>(
            d, d == DEPTH - 1, Whh, bih, bhh, bidx, out);
    }
    k_graph<<<NUM_GRAPHS, HIDDEN>>>(pW, pb, out);
}